// round 14
// baseline (speedup 1.0000x reference)
#include <cuda_runtime.h>
#include <cstdint>

// Interface (R8 ground truth): n_in=5, sizes = 16777216, 32768, 32768, 512, 1
//   d_in[0] inputs   [B=8, K=4096, D=512] fp32
//   d_in[1] mask_ids [B, M=4096] int32
//   d_in[2] keep_ids [B, K=4096] int32
//   d_in[3] mask_emb [D=512] fp32
//   out [B, L=8192, D] fp32
//
// R12/R13 both plateau at 28.2us = ~6.8TB/s (85% HBM) -> memory-system
// ceiling, with the HEAVY stream (128MB writes) randomly scattered.
// This version inverts the permutation (tiny prepass) and GATHERS:
//   writes: perfectly sequential streaming (max row locality)
//   reads:  scattered 2KB rows (lighter 64MB stream)

#define B_ 8
#define K_ 4096
#define M_ 4096
#define L_ (K_ + M_)      // 8192
#define D_ 512
#define V_ (D_ / 4)       // 128 float4 per row
#define RPC 16            // rows per CTA (gather)

__device__ int g_inv[B_ * L_];   // inv[b*L + dst_row] = src_row k, or -1 for mask

__global__ __launch_bounds__(256)
void build_inverse_kernel(const int* __restrict__ mask_ids,
                          const int* __restrict__ keep_ids)
{
    const int idx = blockIdx.x * 256 + threadIdx.x;   // [0, 2*B*K)
    if (idx < B_ * K_) {
        const int b = idx >> 12;                      // / 4096
        g_inv[b * L_ + __ldg(&keep_ids[idx])] = idx & (K_ - 1);
    } else {
        const int j = idx - B_ * K_;                  // [0, B*M)
        const int b = j >> 12;
        g_inv[b * L_ + __ldg(&mask_ids[j])] = -1;
    }
}

__global__ __launch_bounds__(256, 4)
void maskfiller_gather_kernel(const float4* __restrict__ inputs,   // [B*K, 128]
                              const float4* __restrict__ mask_emb, // [128]
                              float4*       __restrict__ out)      // [B*L, 128]
{
    const int r0 = blockIdx.x * RPC;       // first of 16 sequential out rows
    const int b  = r0 >> 13;               // batch (L = 8192)
    const int i0 = r0 & (L_ - 1);
    const int t  = threadIdx.x;
    const int j  = t & (V_ - 1);           // float4 column 0..127
    const int rs = t >> 7;                 // row sub-slot 0/1

    const float4 emb = __ldg(&mask_emb[j]);
    const int inv_base = b * L_ + i0 + rs;
    const size_t in_base  = (size_t)b * K_;
    const size_t out_base = (size_t)b * L_ + i0 + rs;

    // Fetch the 8 source ids (warp-uniform broadcasts, L1/L2 hot).
    int src[8];
    #pragma unroll
    for (int u = 0; u < 8; ++u)
        src[u] = __ldg(&g_inv[inv_base + 2 * u]);

    // 8 independent scattered 2KB-row reads (or emb broadcast).
    float4 v[8];
    #pragma unroll
    for (int u = 0; u < 8; ++u)
        v[u] = (src[u] >= 0) ? __ldcs(&inputs[(in_base + src[u]) * V_ + j]) : emb;

    // 8 perfectly sequential streaming stores (CTA covers 32KB contiguous).
    #pragma unroll
    for (int u = 0; u < 8; ++u)
        __stcs(&out[(out_base + 2 * u) * V_ + j], v[u]);
}

extern "C" void kernel_launch(void* const* d_in, const int* in_sizes, int n_in,
                              void* d_out, int out_size)
{
    const float4* inputs   = (const float4*)d_in[0];
    const int*    mask_ids = (const int*)   d_in[1];
    const int*    keep_ids = (const int*)   d_in[2];
    const float4* mask_emb = (const float4*)d_in[3];
    float4*       out      = (float4*)d_out;
    (void)in_sizes; (void)n_in; (void)out_size;

    build_inverse_kernel<<<(2 * B_ * K_) / 256, 256>>>(mask_ids, keep_ids);
    maskfiller_gather_kernel<<<(B_ * L_) / RPC, 256>>>(inputs, mask_emb, out);
}

// round 15
// speedup vs baseline: 1.0789x; 1.0789x over previous
#include <cuda_runtime.h>
#include <cstdint>

// Interface (R8 ground truth): n_in=5, sizes = 16777216, 32768, 32768, 512, 1
//   d_in[0] inputs   [B=8, K=4096, D=512] fp32
//   d_in[1] mask_ids [B, M=4096] int32
//   d_in[2] keep_ids [B, K=4096] int32
//   d_in[3] mask_emb [D=512] fp32
//   out [B, L=8192, D] fp32
//
// Evidence: scatter register-path and TMA-bulk both plateau at 28.2us;
// gather regressed. Only front-batched per-thread MLP has moved DRAM%
// (MLP4->8: 53%->64%). This version: MLP 16 (32 rows/CTA, 256 threads,
// 16 independent float4 copies per thread). CTAs stay uniformly keep-
// or mask-typed (K, M divisible by 32).

#define B_ 8
#define K_ 4096
#define M_ 4096
#define L_ (K_ + M_)      // 8192
#define D_ 512
#define V_ (D_ / 4)       // 128 float4 per row
#define RPC 32            // rows per CTA
#define U_  16            // independent copies per thread

__global__ __launch_bounds__(256, 2)
void maskfiller_scatter32_kernel(const float4* __restrict__ inputs,   // [B*K, 128]
                                 const int*    __restrict__ mask_ids, // [B,M]
                                 const int*    __restrict__ keep_ids, // [B,K]
                                 const float4* __restrict__ mask_emb, // [128]
                                 float4*       __restrict__ out)      // [B*L, 128]
{
    const int r0 = blockIdx.x * RPC;       // first of 32 global rows
    const int b  = r0 >> 13;               // batch (L = 8192)
    const int i0 = r0 & (L_ - 1);          // row-in-batch of first row
    const int t  = threadIdx.x;
    const int j  = t & (V_ - 1);           // float4 column 0..127
    const int rs = t >> 7;                 // row sub-slot 0/1

    const size_t out_base = (size_t)b * L_;

    if (i0 < K_) {
        // ---- keep CTA: copy 32 rows of inputs to scattered out rows ----
        const int kbase = b * K_ + i0 + rs;
        int ids[U_];
        float4 v[U_];
        #pragma unroll
        for (int u = 0; u < U_; ++u)
            ids[u] = __ldg(&keep_ids[kbase + 2 * u]);
        #pragma unroll
        for (int u = 0; u < U_; ++u)
            v[u] = __ldcs(&inputs[(size_t)(kbase + 2 * u) * V_ + j]);
        #pragma unroll
        for (int u = 0; u < U_; ++u)
            __stcs(&out[(out_base + ids[u]) * V_ + j], v[u]);
    } else {
        // ---- mask CTA: broadcast embedding to 32 scattered out rows ----
        const int mbase = b * M_ + (i0 - K_) + rs;
        const float4 v = __ldg(&mask_emb[j]);
        int ids[U_];
        #pragma unroll
        for (int u = 0; u < U_; ++u)
            ids[u] = __ldg(&mask_ids[mbase + 2 * u]);
        #pragma unroll
        for (int u = 0; u < U_; ++u)
            __stcs(&out[(out_base + ids[u]) * V_ + j], v);
    }
}

extern "C" void kernel_launch(void* const* d_in, const int* in_sizes, int n_in,
                              void* d_out, int out_size)
{
    const float4* inputs   = (const float4*)d_in[0];
    const int*    mask_ids = (const int*)   d_in[1];
    const int*    keep_ids = (const int*)   d_in[2];
    const float4* mask_emb = (const float4*)d_in[3];
    float4*       out      = (float4*)d_out;
    (void)in_sizes; (void)n_in; (void)out_size;

    maskfiller_scatter32_kernel<<<(B_ * L_) / RPC, 256>>>(inputs, mask_ids, keep_ids, mask_emb, out);
}